// round 4
// baseline (speedup 1.0000x reference)
#include <cuda_runtime.h>
#include <cstdint>

#define DI __device__ __forceinline__

constexpr int D = 128, G = 8, F = 80, A = 18;
constexpr int BM = 128, THREADS = 256;

// strides in words; s mod 32 ∈ {4,12,20,28} makes fragment LDS conflict-free
constexpr int KS = 68;   // layer-1 half-K stride (64 cols)   68 % 32 = 4
constexpr int HS = 84;   // hidden / weight stride (80 cols)  84 % 32 = 20

// smem layout (floats)
constexpr int OFF_H1   = 0;             // h1 / h3           : 128*84
constexpr int OFF_H2   = BM * HS;       // state-half / h2   : 128*84 (stride 68 for state)
constexpr int OFF_W    = 2 * BM * HS;   // weight staging    : 80*84 (stride 68 for L1)
constexpr int OFF_BIAS = OFF_W + F * HS;
constexpr int NBIAS    = G * F + F + F + G * A;  // 944
constexpr int OFF_IDX  = OFF_BIAS + NBIAS;
constexpr int SMEM_FLOATS = OFF_IDX + BM;
constexpr int SMEM_BYTES  = SMEM_FLOATS * 4;     // ~117 KB -> 1 CTA/SM

DI uint32_t tf32b(float x) {
    uint32_t r; asm("cvt.rna.tf32.f32 %0, %1;" : "=r"(r) : "f"(x));
    return r;
}
DI float tf32f(float x) { return __uint_as_float(tf32b(x)); }
DI float4 tf32v(float4 v) {
    v.x = tf32f(v.x); v.y = tf32f(v.y); v.z = tf32f(v.z); v.w = tf32f(v.w);
    return v;
}

DI void mma8(float* c, uint32_t a0, uint32_t a1, uint32_t a2, uint32_t a3,
             uint32_t b0, uint32_t b1) {
    asm("mma.sync.aligned.m16n8k8.row.col.f32.tf32.tf32.f32 "
        "{%0,%1,%2,%3}, {%4,%5,%6,%7}, {%8,%9}, {%0,%1,%2,%3};"
        : "+f"(c[0]), "+f"(c[1]), "+f"(c[2]), "+f"(c[3])
        : "r"(a0), "r"(a1), "r"(a2), "r"(a3), "r"(b0), "r"(b1));
}

__global__ __launch_bounds__(THREADS, 1)
void fused_kernel(const float* __restrict__ state, const int* __restrict__ idx,
                  const float* __restrict__ W1, const float* __restrict__ b1,
                  const float* __restrict__ W2, const float* __restrict__ b2,
                  const float* __restrict__ W3, const float* __restrict__ b3,
                  const float* __restrict__ W4, const float* __restrict__ b4,
                  float* __restrict__ out, int nTotal)
{
    extern __shared__ float sm[];
    float* H1 = sm + OFF_H1;
    float* H2 = sm + OFF_H2;   // doubles as state-half staging (stride KS)
    float* SW = sm + OFF_W;
    float* sb = sm + OFF_BIAS;
    int*   sIdx = (int*)(sm + OFF_IDX);

    const int tid  = threadIdx.x;
    const int lane = tid & 31;
    const int wid  = tid >> 5;
    const int gid  = lane >> 2;   // group id 0..7
    const int tig  = lane & 3;    // thread in group
    const int r0   = wid * 16 + gid;
    const int r1   = r0 + 8;

    const int mBase  = blockIdx.x * BM;
    const int nValid = min(BM, nTotal - mBase);

    if (tid < BM) sIdx[tid] = (tid < nValid) ? idx[mBase + tid] : -1;
    for (int it = tid; it < NBIAS; it += THREADS) {
        float v;
        if (it < 640)      v = b1[it];
        else if (it < 720) v = b2[it - 640];
        else if (it < 800) v = b3[it - 720];
        else               v = b4[it - 800];
        sb[it] = v;
    }
    __syncthreads();

    const int gLo = sIdx[0];
    const int gHi = sIdx[nValid - 1];
    const int myG0 = sIdx[r0];
    const int myG1 = sIdx[r1];

    float acc[10][4];

    // ================= Layer 1: h1 = relu(state @ W1[g]^T + b1[g]) -> H1 =================
    for (int g = gLo; g <= gHi; ++g) {
        #pragma unroll
        for (int nt = 0; nt < 10; ++nt)
            #pragma unroll
            for (int q = 0; q < 4; ++q) acc[nt][q] = 0.f;

        #pragma unroll
        for (int h = 0; h < 2; ++h) {
            __syncthreads(); // previous consumers of H2 / SW done
            // stage state half: 128 x 64 tf32, stride KS
            #pragma unroll
            for (int it = 0; it < 8; ++it) {
                int flat = tid + it * THREADS;  // 0..2047
                int m = flat >> 4, c4 = flat & 15;
                float4 v = make_float4(0.f, 0.f, 0.f, 0.f);
                if (m < nValid)
                    v = ((const float4*)state)[(size_t)(mBase + m) * 32 + h * 16 + c4];
                *(float4*)(H2 + m * KS + c4 * 4) = tf32v(v);
            }
            // stage W1[g] half: 80 x 64 tf32, stride KS ([n][k] native)
            #pragma unroll
            for (int it = 0; it < 5; ++it) {
                int flat = tid + it * THREADS;  // 0..1279
                int n = flat >> 4, c4 = flat & 15;
                float4 v = ((const float4*)W1)[(size_t)(g * F + n) * 32 + h * 16 + c4];
                *(float4*)(SW + n * KS + c4 * 4) = tf32v(v);
            }
            __syncthreads();

            // A fragments (8 k-steps)
            uint32_t af[8][4];
            #pragma unroll
            for (int ks = 0; ks < 8; ++ks) {
                af[ks][0] = __float_as_uint(H2[r0 * KS + ks * 8 + tig]);
                af[ks][1] = __float_as_uint(H2[r1 * KS + ks * 8 + tig]);
                af[ks][2] = __float_as_uint(H2[r0 * KS + ks * 8 + tig + 4]);
                af[ks][3] = __float_as_uint(H2[r1 * KS + ks * 8 + tig + 4]);
            }
            #pragma unroll
            for (int nt = 0; nt < 10; ++nt) {
                int bb = (nt * 8 + gid) * KS;
                #pragma unroll
                for (int ks = 0; ks < 8; ++ks) {
                    uint32_t b0 = __float_as_uint(SW[bb + ks * 8 + tig]);
                    uint32_t bv = __float_as_uint(SW[bb + ks * 8 + tig + 4]);
                    mma8(acc[nt], af[ks][0], af[ks][1], af[ks][2], af[ks][3], b0, bv);
                }
            }
        }
        // masked epilogue -> H1 (tf32-rounded, ready as A operand)
        if (myG0 == g) {
            #pragma unroll
            for (int nt = 0; nt < 10; ++nt) {
                int c = nt * 8 + 2 * tig;
                H1[r0 * HS + c]     = tf32f(fmaxf(acc[nt][0] + sb[g * F + c], 0.f));
                H1[r0 * HS + c + 1] = tf32f(fmaxf(acc[nt][1] + sb[g * F + c + 1], 0.f));
            }
        }
        if (myG1 == g) {
            #pragma unroll
            for (int nt = 0; nt < 10; ++nt) {
                int c = nt * 8 + 2 * tig;
                H1[r1 * HS + c]     = tf32f(fmaxf(acc[nt][2] + sb[g * F + c], 0.f));
                H1[r1 * HS + c + 1] = tf32f(fmaxf(acc[nt][3] + sb[g * F + c + 1], 0.f));
            }
        }
    }

    // ================= Layers 2 & 3: h = relu(h @ W^T + b) =================
    #pragma unroll
    for (int l = 0; l < 2; ++l) {
        const float* src = l ? H2 : H1;
        float*       dst = l ? H1 : H2;
        const float* Wg  = l ? W3 : W2;
        const int    bo  = l ? 720 : 640;

        __syncthreads(); // prior reads of SW and dst done
        for (int flat = tid; flat < F * 20; flat += THREADS) {
            int n = flat / 20, c4 = flat - n * 20;
            float4 v = ((const float4*)Wg)[n * 20 + c4];
            *(float4*)(SW + n * HS + c4 * 4) = tf32v(v);
        }
        __syncthreads();

        #pragma unroll
        for (int nt = 0; nt < 10; ++nt)
            #pragma unroll
            for (int q = 0; q < 4; ++q) acc[nt][q] = 0.f;

        uint32_t af[10][4];
        #pragma unroll
        for (int ks = 0; ks < 10; ++ks) {
            af[ks][0] = __float_as_uint(src[r0 * HS + ks * 8 + tig]);
            af[ks][1] = __float_as_uint(src[r1 * HS + ks * 8 + tig]);
            af[ks][2] = __float_as_uint(src[r0 * HS + ks * 8 + tig + 4]);
            af[ks][3] = __float_as_uint(src[r1 * HS + ks * 8 + tig + 4]);
        }
        #pragma unroll
        for (int nt = 0; nt < 10; ++nt) {
            int bb = (nt * 8 + gid) * HS;
            #pragma unroll
            for (int ks = 0; ks < 10; ++ks) {
                uint32_t b0 = __float_as_uint(SW[bb + ks * 8 + tig]);
                uint32_t bv = __float_as_uint(SW[bb + ks * 8 + tig + 4]);
                mma8(acc[nt], af[ks][0], af[ks][1], af[ks][2], af[ks][3], b0, bv);
            }
        }
        #pragma unroll
        for (int nt = 0; nt < 10; ++nt) {
            int c = nt * 8 + 2 * tig;
            dst[r0 * HS + c]     = tf32f(fmaxf(acc[nt][0] + sb[bo + c], 0.f));
            dst[r0 * HS + c + 1] = tf32f(fmaxf(acc[nt][1] + sb[bo + c + 1], 0.f));
            dst[r1 * HS + c]     = tf32f(fmaxf(acc[nt][2] + sb[bo + c], 0.f));
            dst[r1 * HS + c + 1] = tf32f(fmaxf(acc[nt][3] + sb[bo + c + 1], 0.f));
        }
    }

    // ================= Layer 4: q = h3 @ W4[g]^T + b4[g]  (h3 in H1) =================
    __syncthreads(); // h3 writes visible to all warps
    uint32_t af4[10][4];
    #pragma unroll
    for (int ks = 0; ks < 10; ++ks) {
        af4[ks][0] = __float_as_uint(H1[r0 * HS + ks * 8 + tig]);
        af4[ks][1] = __float_as_uint(H1[r1 * HS + ks * 8 + tig]);
        af4[ks][2] = __float_as_uint(H1[r0 * HS + ks * 8 + tig + 4]);
        af4[ks][3] = __float_as_uint(H1[r1 * HS + ks * 8 + tig + 4]);
    }

    for (int g = gLo; g <= gHi; ++g) {
        __syncthreads(); // prior SW readers done
        for (int flat = tid; flat < A * 20; flat += THREADS) {
            int n = flat / 20, c4 = flat - n * 20;
            float4 v = ((const float4*)W4)[(size_t)(g * A + n) * 20 + c4];
            *(float4*)(SW + n * HS + c4 * 4) = tf32v(v);
        }
        __syncthreads();

        float a4[3][4];
        #pragma unroll
        for (int nt = 0; nt < 3; ++nt)
            #pragma unroll
            for (int q = 0; q < 4; ++q) a4[nt][q] = 0.f;

        #pragma unroll
        for (int nt = 0; nt < 3; ++nt) {
            int bb = (nt * 8 + gid) * HS; // rows >= 18 read stale-but-finite data; masked below
            #pragma unroll
            for (int ks = 0; ks < 10; ++ks) {
                uint32_t b0 = __float_as_uint(SW[bb + ks * 8 + tig]);
                uint32_t bv = __float_as_uint(SW[bb + ks * 8 + tig + 4]);
                mma8(a4[nt], af4[ks][0], af4[ks][1], af4[ks][2], af4[ks][3], b0, bv);
            }
        }
        #pragma unroll
        for (int nt = 0; nt < 3; ++nt) {
            int c = nt * 8 + 2 * tig;
            if (c < A) {
                if (myG0 == g) {
                    float* o = out + (size_t)(mBase + r0) * A + c;
                    o[0] = a4[nt][0] + sb[800 + g * A + c];
                    if (c + 1 < A) o[1] = a4[nt][1] + sb[800 + g * A + c + 1];
                }
                if (myG1 == g) {
                    float* o = out + (size_t)(mBase + r1) * A + c;
                    o[0] = a4[nt][2] + sb[800 + g * A + c];
                    if (c + 1 < A) o[1] = a4[nt][3] + sb[800 + g * A + c + 1];
                }
            }
        }
    }
}

extern "C" void kernel_launch(void* const* d_in, const int* in_sizes, int n_in,
                              void* d_out, int out_size) {
    const float* state = (const float*)d_in[0];
    const int*   idx   = (const int*)d_in[1];
    const float* W1    = (const float*)d_in[2];
    const float* b1    = (const float*)d_in[3];
    const float* W2    = (const float*)d_in[4];
    const float* b2    = (const float*)d_in[5];
    const float* W3    = (const float*)d_in[6];
    const float* b3    = (const float*)d_in[7];
    const float* W4    = (const float*)d_in[8];
    const float* b4    = (const float*)d_in[9];
    float* out = (float*)d_out;

    const int B = in_sizes[1];

    cudaFuncSetAttribute(fused_kernel, cudaFuncAttributeMaxDynamicSharedMemorySize, SMEM_BYTES);
    int grid = (B + BM - 1) / BM;
    fused_kernel<<<grid, THREADS, SMEM_BYTES>>>(state, idx, W1, b1, W2, b2, W3, b3,
                                                W4, b4, out, B);
}

// round 5
// speedup vs baseline: 1.5428x; 1.5428x over previous
#include <cuda_runtime.h>
#include <cstdint>

#define DI __device__ __forceinline__

constexpr int D = 128, G = 8, F = 80, A = 18;
constexpr int BM = 128, THREADS = 256;

// strides in words; s mod 8 == 4 makes fragment LDS conflict-free
constexpr int KS = 68;   // layer-1 half-K stride (64 cols)
constexpr int HS = 84;   // hidden / weight stride (80 cols)

// smem layout (floats)
constexpr int OFF_H1   = 0;             // h1 / h3           : 128*84
constexpr int OFF_H2   = BM * HS;       // state-half / h2   : 128*84 (stride 68 for state)
constexpr int OFF_W    = 2 * BM * HS;   // weight staging    : 80*84 (stride 68 for L1)
constexpr int OFF_BIAS = OFF_W + F * HS;  // b2 (80) + b3 (80) only
constexpr int OFF_IDX  = OFF_BIAS + 2 * F;
constexpr int SMEM_FLOATS = OFF_IDX + BM;
constexpr int SMEM_BYTES  = SMEM_FLOATS * 4;   // 114048 B -> 2 CTAs/SM

DI uint32_t tf32b(float x) {
    uint32_t r; asm("cvt.rna.tf32.f32 %0, %1;" : "=r"(r) : "f"(x));
    return r;
}
DI float tf32f(float x) { return __uint_as_float(tf32b(x)); }
DI float4 tf32v(float4 v) {
    v.x = tf32f(v.x); v.y = tf32f(v.y); v.z = tf32f(v.z); v.w = tf32f(v.w);
    return v;
}

DI void mma8(float* c, uint32_t a0, uint32_t a1, uint32_t a2, uint32_t a3,
             uint32_t b0, uint32_t b1) {
    asm("mma.sync.aligned.m16n8k8.row.col.f32.tf32.tf32.f32 "
        "{%0,%1,%2,%3}, {%4,%5,%6,%7}, {%8,%9}, {%0,%1,%2,%3};"
        : "+f"(c[0]), "+f"(c[1]), "+f"(c[2]), "+f"(c[3])
        : "r"(a0), "r"(a1), "r"(a2), "r"(a3), "r"(b0), "r"(b1));
}

__global__ __launch_bounds__(THREADS, 2)
void fused_kernel(const float* __restrict__ state, const int* __restrict__ idx,
                  const float* __restrict__ W1, const float* __restrict__ b1,
                  const float* __restrict__ W2, const float* __restrict__ b2,
                  const float* __restrict__ W3, const float* __restrict__ b3,
                  const float* __restrict__ W4, const float* __restrict__ b4,
                  float* __restrict__ out, int nTotal)
{
    extern __shared__ float sm[];
    float* H1 = sm + OFF_H1;
    float* H2 = sm + OFF_H2;   // doubles as state-half staging (stride KS)
    float* SW = sm + OFF_W;
    float* sb = sm + OFF_BIAS; // [0..79]=b2, [80..159]=b3
    int*   sIdx = (int*)(sm + OFF_IDX);

    const int tid  = threadIdx.x;
    const int lane = tid & 31;
    const int wid  = tid >> 5;
    const int gid  = lane >> 2;   // group id 0..7
    const int tig  = lane & 3;    // thread in group
    const int r0   = wid * 16 + gid;
    const int r1   = r0 + 8;

    const int mBase  = blockIdx.x * BM;
    const int nValid = min(BM, nTotal - mBase);

    if (tid < BM) sIdx[tid] = (tid < nValid) ? idx[mBase + tid] : -1;
    if (tid < 2 * F) sb[tid] = (tid < F) ? b2[tid] : b3[tid - F];
    __syncthreads();

    const int gLo = sIdx[0];
    const int gHi = sIdx[nValid - 1];
    const int myG0 = sIdx[r0];
    const int myG1 = sIdx[r1];

    float acc[10][4];

    // ================= Layer 1: h1 = relu(state @ W1[g]^T + b1[g]) -> H1 =================
    for (int g = gLo; g <= gHi; ++g) {
        #pragma unroll
        for (int nt = 0; nt < 10; ++nt)
            #pragma unroll
            for (int q = 0; q < 4; ++q) acc[nt][q] = 0.f;

        #pragma unroll
        for (int h = 0; h < 2; ++h) {
            __syncthreads(); // previous consumers of H2 / SW done
            // stage state half: 128 x 64 tf32, stride KS
            #pragma unroll
            for (int it = 0; it < 8; ++it) {
                int flat = tid + it * THREADS;  // 0..2047
                int m = flat >> 4, c4 = flat & 15;
                float4 v = make_float4(0.f, 0.f, 0.f, 0.f);
                if (m < nValid)
                    v = ((const float4*)state)[(size_t)(mBase + m) * 32 + h * 16 + c4];
                *(float4*)(H2 + m * KS + c4 * 4) = tf32v(v);
            }
            // stage W1[g] half: 80 x 64 tf32, stride KS ([n][k] native)
            #pragma unroll
            for (int it = 0; it < 5; ++it) {
                int flat = tid + it * THREADS;  // 0..1279
                int n = flat >> 4, c4 = flat & 15;
                float4 v = ((const float4*)W1)[(size_t)(g * F + n) * 32 + h * 16 + c4];
                *(float4*)(SW + n * KS + c4 * 4) = tf32v(v);
            }
            __syncthreads();

            #pragma unroll
            for (int ks = 0; ks < 8; ++ks) {
                uint32_t a0 = __float_as_uint(H2[r0 * KS + ks * 8 + tig]);
                uint32_t a1 = __float_as_uint(H2[r1 * KS + ks * 8 + tig]);
                uint32_t a2 = __float_as_uint(H2[r0 * KS + ks * 8 + tig + 4]);
                uint32_t a3 = __float_as_uint(H2[r1 * KS + ks * 8 + tig + 4]);
                #pragma unroll
                for (int nt = 0; nt < 10; ++nt) {
                    int bb = (nt * 8 + gid) * KS + ks * 8 + tig;
                    mma8(acc[nt], a0, a1, a2, a3,
                         __float_as_uint(SW[bb]), __float_as_uint(SW[bb + 4]));
                }
            }
        }
        // masked epilogue -> H1 (tf32-rounded, ready as A operand)
        if (myG0 == g) {
            #pragma unroll
            for (int nt = 0; nt < 10; ++nt) {
                int c = nt * 8 + 2 * tig;
                H1[r0 * HS + c]     = tf32f(fmaxf(acc[nt][0] + __ldg(&b1[g * F + c]), 0.f));
                H1[r0 * HS + c + 1] = tf32f(fmaxf(acc[nt][1] + __ldg(&b1[g * F + c + 1]), 0.f));
            }
        }
        if (myG1 == g) {
            #pragma unroll
            for (int nt = 0; nt < 10; ++nt) {
                int c = nt * 8 + 2 * tig;
                H1[r1 * HS + c]     = tf32f(fmaxf(acc[nt][2] + __ldg(&b1[g * F + c]), 0.f));
                H1[r1 * HS + c + 1] = tf32f(fmaxf(acc[nt][3] + __ldg(&b1[g * F + c + 1]), 0.f));
            }
        }
    }

    // ================= Layers 2 & 3: h = relu(h @ W^T + b) =================
    #pragma unroll
    for (int l = 0; l < 2; ++l) {
        const float* src = l ? H2 : H1;
        float*       dst = l ? H1 : H2;
        const float* Wg  = l ? W3 : W2;
        const float* bb2 = sb + l * F;

        __syncthreads(); // prior reads of SW and dst done
        for (int flat = tid; flat < F * 20; flat += THREADS) {
            int n = flat / 20, c4 = flat - n * 20;
            float4 v = ((const float4*)Wg)[n * 20 + c4];
            *(float4*)(SW + n * HS + c4 * 4) = tf32v(v);
        }
        __syncthreads();

        #pragma unroll
        for (int nt = 0; nt < 10; ++nt)
            #pragma unroll
            for (int q = 0; q < 4; ++q) acc[nt][q] = 0.f;

        #pragma unroll
        for (int ks = 0; ks < 10; ++ks) {
            uint32_t a0 = __float_as_uint(src[r0 * HS + ks * 8 + tig]);
            uint32_t a1 = __float_as_uint(src[r1 * HS + ks * 8 + tig]);
            uint32_t a2 = __float_as_uint(src[r0 * HS + ks * 8 + tig + 4]);
            uint32_t a3 = __float_as_uint(src[r1 * HS + ks * 8 + tig + 4]);
            #pragma unroll
            for (int nt = 0; nt < 10; ++nt) {
                int bo = (nt * 8 + gid) * HS + ks * 8 + tig;
                mma8(acc[nt], a0, a1, a2, a3,
                     __float_as_uint(SW[bo]), __float_as_uint(SW[bo + 4]));
            }
        }
        #pragma unroll
        for (int nt = 0; nt < 10; ++nt) {
            int c = nt * 8 + 2 * tig;
            dst[r0 * HS + c]     = tf32f(fmaxf(acc[nt][0] + bb2[c], 0.f));
            dst[r0 * HS + c + 1] = tf32f(fmaxf(acc[nt][1] + bb2[c + 1], 0.f));
            dst[r1 * HS + c]     = tf32f(fmaxf(acc[nt][2] + bb2[c], 0.f));
            dst[r1 * HS + c + 1] = tf32f(fmaxf(acc[nt][3] + bb2[c + 1], 0.f));
        }
    }

    // ================= Layer 4: q = h3 @ W4[g]^T + b4[g]  (h3 in H1) =================
    for (int g = gLo; g <= gHi; ++g) {
        __syncthreads(); // h3 writes visible / prior SW readers done
        for (int flat = tid; flat < A * 20; flat += THREADS) {
            int n = flat / 20, c4 = flat - n * 20;
            float4 v = ((const float4*)W4)[(size_t)(g * A + n) * 20 + c4];
            *(float4*)(SW + n * HS + c4 * 4) = tf32v(v);
        }
        __syncthreads();

        float a4[3][4];
        #pragma unroll
        for (int nt = 0; nt < 3; ++nt)
            #pragma unroll
            for (int q = 0; q < 4; ++q) a4[nt][q] = 0.f;

        #pragma unroll
        for (int ks = 0; ks < 10; ++ks) {
            uint32_t a0 = __float_as_uint(H1[r0 * HS + ks * 8 + tig]);
            uint32_t a1 = __float_as_uint(H1[r1 * HS + ks * 8 + tig]);
            uint32_t a2 = __float_as_uint(H1[r0 * HS + ks * 8 + tig + 4]);
            uint32_t a3 = __float_as_uint(H1[r1 * HS + ks * 8 + tig + 4]);
            #pragma unroll
            for (int nt = 0; nt < 3; ++nt) {
                // rows >= 18 read stale-but-finite data; outputs masked below
                int bo = (nt * 8 + gid) * HS + ks * 8 + tig;
                mma8(a4[nt], a0, a1, a2, a3,
                     __float_as_uint(SW[bo]), __float_as_uint(SW[bo + 4]));
            }
        }
        #pragma unroll
        for (int nt = 0; nt < 3; ++nt) {
            int c = nt * 8 + 2 * tig;
            if (c < A) {
                if (myG0 == g) {
                    float* o = out + (size_t)(mBase + r0) * A + c;
                    o[0] = a4[nt][0] + __ldg(&b4[g * A + c]);
                    if (c + 1 < A) o[1] = a4[nt][1] + __ldg(&b4[g * A + c + 1]);
                }
                if (myG1 == g) {
                    float* o = out + (size_t)(mBase + r1) * A + c;
                    o[0] = a4[nt][2] + __ldg(&b4[g * A + c]);
                    if (c + 1 < A) o[1] = a4[nt][3] + __ldg(&b4[g * A + c + 1]);
                }
            }
        }
    }
}

extern "C" void kernel_launch(void* const* d_in, const int* in_sizes, int n_in,
                              void* d_out, int out_size) {
    const float* state = (const float*)d_in[0];
    const int*   idx   = (const int*)d_in[1];
    const float* W1    = (const float*)d_in[2];
    const float* b1    = (const float*)d_in[3];
    const float* W2    = (const float*)d_in[4];
    const float* b2    = (const float*)d_in[5];
    const float* W3    = (const float*)d_in[6];
    const float* b3    = (const float*)d_in[7];
    const float* W4    = (const float*)d_in[8];
    const float* b4    = (const float*)d_in[9];
    float* out = (float*)d_out;

    const int B = in_sizes[1];

    cudaFuncSetAttribute(fused_kernel, cudaFuncAttributeMaxDynamicSharedMemorySize, SMEM_BYTES);
    int grid = (B + BM - 1) / BM;
    fused_kernel<<<grid, THREADS, SMEM_BYTES>>>(state, idx, W1, b1, W2, b2, W3, b3,
                                                W4, b4, out, B);
}

// round 6
// speedup vs baseline: 2.3457x; 1.5205x over previous
#include <cuda_runtime.h>
#include <cstdint>

#define DI __device__ __forceinline__

constexpr int D = 128, G = 8, F = 80, A = 18;
constexpr int BM = 128, THREADS = 256;

constexpr int HS  = 84;  // H stride (80 cols)   84 % 32 = 20 -> conflict-free frags
constexpr int WS  = 44;  // W2/3/4 half stride   44 % 32 = 12
constexpr int W1S = 36;  // W1 quarter stride    36 % 32 = 4
constexpr int SLOT = F * WS;  // 3520 floats per weight slot (max stage: 80x44)

constexpr int OFF_H  = 0;                 // 128*84 = 10752 floats
constexpr int OFF_SW = BM * HS;           // 3 rotating weight slots
constexpr int OFF_SB = OFF_SW + 3 * SLOT; // b2(80) + b3(80)
constexpr int SMEM_FLOATS = OFF_SB + 2 * F;
constexpr int SMEM_BYTES  = SMEM_FLOATS * 4;  // 85888 B -> 2 CTAs/SM

// tf32 pre-rounded weight scratch (filled by prep_kernel)
__device__ __align__(16) float g_W1r[G * F * D];
__device__ __align__(16) float g_W2r[F * F];
__device__ __align__(16) float g_W3r[F * F];
__device__ __align__(16) float g_W4r[G * A * F];

DI uint32_t tf32b(float x) {
    uint32_t r; asm("cvt.rna.tf32.f32 %0, %1;" : "=r"(r) : "f"(x));
    return r;
}
DI float tf32f(float x) { return __uint_as_float(tf32b(x)); }

DI void mma8(float* c, uint32_t a0, uint32_t a1, uint32_t a2, uint32_t a3,
             uint32_t b0, uint32_t b1) {
    asm("mma.sync.aligned.m16n8k8.row.col.f32.tf32.tf32.f32 "
        "{%0,%1,%2,%3}, {%4,%5,%6,%7}, {%8,%9}, {%0,%1,%2,%3};"
        : "+f"(c[0]), "+f"(c[1]), "+f"(c[2]), "+f"(c[3])
        : "r"(a0), "r"(a1), "r"(a2), "r"(a3), "r"(b0), "r"(b1));
}

DI void cpa16(uint32_t dst, const float* src) {
    asm volatile("cp.async.cg.shared.global [%0], [%1], 16;" :: "r"(dst), "l"(src));
}
#define CPA_COMMIT() asm volatile("cp.async.commit_group;" ::: "memory")
#define CPA_WAIT1()  asm volatile("cp.async.wait_group 1;" ::: "memory")

__global__ void prep_kernel(const float* __restrict__ W1, const float* __restrict__ W2,
                            const float* __restrict__ W3, const float* __restrict__ W4) {
    int i = blockIdx.x * blockDim.x + threadIdx.x;
    if (i < G * F * D) g_W1r[i] = tf32f(W1[i]);
    if (i < F * F) { g_W2r[i] = tf32f(W2[i]); g_W3r[i] = tf32f(W3[i]); }
    if (i < G * A * F) g_W4r[i] = tf32f(W4[i]);
}

// stage s -> prefetch its weights into slot s%3 (16B cp.async chunks)
DI void issue_stage(int s, int gLo, int nG, uint32_t swbase, int tid) {
    uint32_t dst0 = swbase + (uint32_t)(s % 3) * (SLOT * 4);
    if (s < 4 * nG) {                       // W1 quarter: 80 rows x 32 floats
        int g = gLo + (s >> 2), q = s & 3;
        const float* src = g_W1r + (size_t)g * F * D + q * 32;
        #pragma unroll
        for (int c = tid; c < 640; c += THREADS) {
            int n = c >> 3, cc = c & 7;
            cpa16(dst0 + n * (W1S * 4) + cc * 16, src + n * D + cc * 4);
        }
    } else {
        int t = s - 4 * nG;
        const float* src; int rows;
        if (t < 2)      { src = g_W2r + (t & 1) * 40; rows = F; }
        else if (t < 4) { src = g_W3r + (t & 1) * 40; rows = F; }
        else {
            int u = t - 4; int g = gLo + (u >> 1);
            src = g_W4r + (size_t)g * A * F + (u & 1) * 40; rows = A;
        }
        int nch = rows * 10;                // rows x 40 floats, stride WS
        for (int c = tid; c < nch; c += THREADS) {
            int n = c / 10, cc = c - n * 10;
            cpa16(dst0 + n * (WS * 4) + cc * 16, src + n * F + cc * 4);
        }
    }
}

__global__ __launch_bounds__(THREADS, 2)
void fused_kernel(const float* __restrict__ state, const int* __restrict__ idx,
                  const float* __restrict__ b1, const float* __restrict__ b2,
                  const float* __restrict__ b3, const float* __restrict__ b4,
                  float* __restrict__ out, int nTotal)
{
    extern __shared__ float sm[];
    float* H  = sm + OFF_H;
    float* sb = sm + OFF_SB;  // [0..79]=b2, [80..159]=b3

    uint32_t su;
    asm("{ .reg .u64 t; cvta.to.shared.u64 t, %1; cvt.u32.u64 %0, t; }"
        : "=r"(su) : "l"(sm));
    const uint32_t swbase = su + OFF_SW * 4;

    const int tid  = threadIdx.x;
    const int lane = tid & 31;
    const int wid  = tid >> 5;
    const int gid  = lane >> 2;
    const int tig  = lane & 3;
    const int r0   = wid * 16 + gid;
    const int r1   = r0 + 8;

    const int mBase  = blockIdx.x * BM;
    const int nValid = min(BM, nTotal - mBase);

    const int gLo = __ldg(&idx[mBase]);
    const int gHi = __ldg(&idx[mBase + nValid - 1]);
    const int myG0 = (r0 < nValid) ? __ldg(&idx[mBase + r0]) : -1;
    const int myG1 = (r1 < nValid) ? __ldg(&idx[mBase + r1]) : -1;
    const int nG = gHi - gLo + 1;
    const int nStages = 6 * nG + 4;  // 4*nG (W1) + 2 (W2) + 2 (W3) + 2*nG (W4)

    if (tid < 2 * F) sb[tid] = (tid < F) ? b2[tid] : b3[tid - F];

    // clamped state row pointers for A fragments
    const float* st0 = state + (size_t)min(mBase + r0, nTotal - 1) * D;
    const float* st1 = state + (size_t)min(mBase + r1, nTotal - 1) * D;

    // prologue: prefetch stages 0, 1
    issue_stage(0, gLo, nG, swbase, tid); CPA_COMMIT();
    issue_stage(1, gLo, nG, swbase, tid); CPA_COMMIT();

    float acc[10][4];

    for (int s = 0; s < nStages; ++s) {
        CPA_WAIT1();
        __syncthreads();
        const float* SWp = sm + OFF_SW + (s % 3) * SLOT;

        if (s < 4 * nG) {
            // ---------- Layer 1, quarter q of game g ----------
            int g = gLo + (s >> 2), q = s & 3;
            if (q == 0) {
                #pragma unroll
                for (int nt = 0; nt < 10; ++nt)
                    #pragma unroll
                    for (int i = 0; i < 4; ++i) acc[nt][i] = 0.f;
            }
            #pragma unroll
            for (int kl = 0; kl < 4; ++kl) {
                int kb = q * 32 + kl * 8;
                uint32_t a0 = tf32b(__ldg(st0 + kb + tig));
                uint32_t a1 = tf32b(__ldg(st1 + kb + tig));
                uint32_t a2 = tf32b(__ldg(st0 + kb + tig + 4));
                uint32_t a3 = tf32b(__ldg(st1 + kb + tig + 4));
                #pragma unroll
                for (int nt = 0; nt < 10; ++nt) {
                    const float* bp = SWp + (nt * 8 + gid) * W1S + kl * 8 + tig;
                    mma8(acc[nt], a0, a1, a2, a3,
                         __float_as_uint(bp[0]), __float_as_uint(bp[4]));
                }
            }
            if (q == 3) {  // masked epilogue -> H (tf32-rounded)
                if (myG0 == g) {
                    #pragma unroll
                    for (int nt = 0; nt < 10; ++nt) {
                        int c = nt * 8 + 2 * tig;
                        float2 w = make_float2(
                            tf32f(fmaxf(acc[nt][0] + __ldg(&b1[g * F + c]), 0.f)),
                            tf32f(fmaxf(acc[nt][1] + __ldg(&b1[g * F + c + 1]), 0.f)));
                        *(float2*)(H + r0 * HS + c) = w;
                    }
                }
                if (myG1 == g) {
                    #pragma unroll
                    for (int nt = 0; nt < 10; ++nt) {
                        int c = nt * 8 + 2 * tig;
                        float2 w = make_float2(
                            tf32f(fmaxf(acc[nt][2] + __ldg(&b1[g * F + c]), 0.f)),
                            tf32f(fmaxf(acc[nt][3] + __ldg(&b1[g * F + c + 1]), 0.f)));
                        *(float2*)(H + r1 * HS + c) = w;
                    }
                }
            }
        } else if (s - 4 * nG < 4) {
            // ---------- Layers 2 & 3, half h ----------
            int t = s - 4 * nG;
            int l = t >> 1, h = t & 1;
            if (h == 0) {
                #pragma unroll
                for (int nt = 0; nt < 10; ++nt)
                    #pragma unroll
                    for (int i = 0; i < 4; ++i) acc[nt][i] = 0.f;
            }
            #pragma unroll
            for (int kl = 0; kl < 5; ++kl) {
                int kb = h * 40 + kl * 8;
                uint32_t a0 = __float_as_uint(H[r0 * HS + kb + tig]);
                uint32_t a1 = __float_as_uint(H[r1 * HS + kb + tig]);
                uint32_t a2 = __float_as_uint(H[r0 * HS + kb + tig + 4]);
                uint32_t a3 = __float_as_uint(H[r1 * HS + kb + tig + 4]);
                #pragma unroll
                for (int nt = 0; nt < 10; ++nt) {
                    const float* bp = SWp + (nt * 8 + gid) * WS + kl * 8 + tig;
                    mma8(acc[nt], a0, a1, a2, a3,
                         __float_as_uint(bp[0]), __float_as_uint(bp[4]));
                }
            }
            if (h == 1) {  // in-place epilogue (warp-private rows)
                #pragma unroll
                for (int nt = 0; nt < 10; ++nt) {
                    int c = nt * 8 + 2 * tig;
                    float2 w0 = make_float2(
                        tf32f(fmaxf(acc[nt][0] + sb[l * F + c], 0.f)),
                        tf32f(fmaxf(acc[nt][1] + sb[l * F + c + 1], 0.f)));
                    float2 w1 = make_float2(
                        tf32f(fmaxf(acc[nt][2] + sb[l * F + c], 0.f)),
                        tf32f(fmaxf(acc[nt][3] + sb[l * F + c + 1], 0.f)));
                    *(float2*)(H + r0 * HS + c) = w0;
                    *(float2*)(H + r1 * HS + c) = w1;
                }
            }
        } else {
            // ---------- Layer 4, half h of game g ----------
            int u = s - 4 * nG - 4;
            int g = gLo + (u >> 1), h = u & 1;
            if (h == 0) {
                #pragma unroll
                for (int nt = 0; nt < 3; ++nt)
                    #pragma unroll
                    for (int i = 0; i < 4; ++i) acc[nt][i] = 0.f;
            }
            #pragma unroll
            for (int kl = 0; kl < 5; ++kl) {
                int kb = h * 40 + kl * 8;
                uint32_t a0 = __float_as_uint(H[r0 * HS + kb + tig]);
                uint32_t a1 = __float_as_uint(H[r1 * HS + kb + tig]);
                uint32_t a2 = __float_as_uint(H[r0 * HS + kb + tig + 4]);
                uint32_t a3 = __float_as_uint(H[r1 * HS + kb + tig + 4]);
                #pragma unroll
                for (int nt = 0; nt < 3; ++nt) {
                    // B rows >= 18 hold stale finite data; outputs masked below
                    const float* bp = SWp + (nt * 8 + gid) * WS + kl * 8 + tig;
                    mma8(acc[nt], a0, a1, a2, a3,
                         __float_as_uint(bp[0]), __float_as_uint(bp[4]));
                }
            }
            if (h == 1) {
                #pragma unroll
                for (int nt = 0; nt < 3; ++nt) {
                    int c = nt * 8 + 2 * tig;
                    if (c + 1 < A) {
                        if (myG0 == g) {
                            float2 v = make_float2(acc[nt][0] + __ldg(&b4[g * A + c]),
                                                   acc[nt][1] + __ldg(&b4[g * A + c + 1]));
                            *(float2*)(out + (size_t)(mBase + r0) * A + c) = v;
                        }
                        if (myG1 == g) {
                            float2 v = make_float2(acc[nt][2] + __ldg(&b4[g * A + c]),
                                                   acc[nt][3] + __ldg(&b4[g * A + c + 1]));
                            *(float2*)(out + (size_t)(mBase + r1) * A + c) = v;
                        }
                    }
                }
            }
        }

        if (s + 2 < nStages) issue_stage(s + 2, gLo, nG, swbase, tid);
        CPA_COMMIT();  // empty groups near the tail keep counts aligned
    }
}

extern "C" void kernel_launch(void* const* d_in, const int* in_sizes, int n_in,
                              void* d_out, int out_size) {
    const float* state = (const float*)d_in[0];
    const int*   idx   = (const int*)d_in[1];
    const float* W1    = (const float*)d_in[2];
    const float* b1    = (const float*)d_in[3];
    const float* W2    = (const float*)d_in[4];
    const float* b2    = (const float*)d_in[5];
    const float* W3    = (const float*)d_in[6];
    const float* b3    = (const float*)d_in[7];
    const float* W4    = (const float*)d_in[8];
    const float* b4    = (const float*)d_in[9];
    float* out = (float*)d_out;

    const int B = in_sizes[1];

    prep_kernel<<<(G * F * D + 255) / 256, 256>>>(W1, W2, W3, W4);

    cudaFuncSetAttribute(fused_kernel, cudaFuncAttributeMaxDynamicSharedMemorySize, SMEM_BYTES);
    int grid = (B + BM - 1) / BM;
    fused_kernel<<<grid, THREADS, SMEM_BYTES>>>(state, idx, b1, b2, b3, b4, out, B);
}